// round 8
// baseline (speedup 1.0000x reference)
#include <cuda_runtime.h>
#include <math.h>

#define BB    16
#define NBB   512
#define KK    32
#define NBLK  (BB * NBB)      /* 8192 (b, nb) blocks */
#define GW    0.3f
#define GRID  1024            /* 1 warp per block; <=7 CTAs/SM -> all resident */
#define TPB   256
#define CTA_PER_BATCH 64

/* ---- scratch (device globals; no allocation) ---- */
__device__ float2 g_vp     [NBLK];  /* (cnt_vld, sum_vld_p) */
__device__ float4 g_uncs   [NBLK];  /* (sum_unc_p, sum_unc_p2, cnt_unc, 0) */
__device__ float2 g_cta_bce[GRID];  /* per-CTA (bce_sum, bce_cnt) */
__device__ float2 g_cta_sq [GRID];  /* per-CTA (sq, qu) — one batch per CTA */
__device__ unsigned int g_batch_bar[BB];
__device__ unsigned int g_done = 0;

__device__ __forceinline__ float warp_sum(float v) {
    #pragma unroll
    for (int o = 16; o > 0; o >>= 1) v += __shfl_down_sync(0xFFFFFFFFu, v, o);
    return v;
}

__device__ __forceinline__ unsigned int arrive_acq_rel(unsigned int* ctr) {
    unsigned int old;
    asm volatile("atom.acq_rel.gpu.add.u32 %0, [%1], 1;"
                 : "=r"(old) : "l"(ctr) : "memory");
    return old;
}

__global__ void __launch_bounds__(TPB, 8) fused_kernel(
    const float4* __restrict__ logits,
    const float4* __restrict__ targets,
    const int4*   __restrict__ sup_mask,
    const int4*   __restrict__ ign_mask,
    const int*    __restrict__ kv_indices,
    const int*    __restrict__ kv_num_blocks,
    float*        __restrict__ out)
{
    const int lane  = threadIdx.x & 31;
    const int wid   = threadIdx.x >> 5;
    const int batch = blockIdx.x >> 6;                 /* 64 CTAs per batch */
    const int base  = batch << 9;                      /* batch * 512       */
    const int blk   = base + ((blockIdx.x & 63) << 3) + wid;  /* 1 block / warp */

    __shared__ float2 sh_bce[8];
    __shared__ float2 sh_sq[8];
    __shared__ float  bsq[BB], bqu[BB];
    __shared__ float  s_bce;
    __shared__ bool   is_last;

    /* ---- prefetch phase-B operands (latency hides under phase A) ---- */
    const int idx = kv_indices[blk * KK + lane];
    const int knb = kv_num_blocks[blk];

    /* ============ Phase A: exactly 1 block per warp (4x LDG.128) ============ */
    {
        const int v = blk * 32 + lane;                 /* float4 index */
        const float4 x4 = logits[v];
        const float4 t4 = targets[v];
        const int4   s4 = sup_mask[v];
        const int4   i4 = ign_mask[v];

        float svp = 0.f, sup_ = 0.f, sup2 = 0.f, bce = 0.f, cnts = 0.f;
        const float xs[4] = {x4.x, x4.y, x4.z, x4.w};
        const float ts[4] = {t4.x, t4.y, t4.z, t4.w};
        const int   ss[4] = {s4.x, s4.y, s4.z, s4.w};
        const int   is_[4]= {i4.x, i4.y, i4.z, i4.w};

        #pragma unroll
        for (int j = 0; j < 4; ++j) {
            const float x  = xs[j];
            const bool  su = ss[j] != 0;
            const bool  ig = is_[j] != 0;
            const bool  vld = !ig;
            const bool  unc = vld && !su;
            const float p = 1.0f / (1.0f + __expf(-x));
            if (vld) svp += p;
            if (unc) { sup_ += p; sup2 += p * p; }
            if (su)  bce += fmaxf(x, 0.0f) - x * ts[j] + __logf(1.0f + __expf(-fabsf(x)));
            /* pack counts: vld + 256*unc + 65536*sup (sum < 2^24, exact) */
            cnts += (vld ? 1.0f : 0.0f) + (unc ? 256.0f : 0.0f) + (su ? 65536.0f : 0.0f);
        }

        svp  = warp_sum(svp);
        sup_ = warp_sum(sup_);
        sup2 = warp_sum(sup2);
        bce  = warp_sum(bce);
        cnts = warp_sum(cnts);

        if (lane == 0) {
            const int ci = (int)cnts;
            g_vp  [blk] = make_float2((float)(ci & 255), svp);
            g_uncs[blk] = make_float4(sup_, sup2, (float)((ci >> 8) & 255), 0.f);
            sh_bce[wid] = make_float2(bce, (float)(ci >> 16));
        }
    }
    __syncthreads();
    if (threadIdx.x == 0) {
        float s = 0.f, c = 0.f;
        #pragma unroll
        for (int w = 0; w < 8; ++w) { s += sh_bce[w].x; c += sh_bce[w].y; }
        g_cta_bce[blockIdx.x] = make_float2(s, c);
        /* per-batch barrier: the 64 CTAs of this batch */
        const unsigned int old = arrive_acq_rel(&g_batch_bar[batch]);
        if (old != CTA_PER_BATCH - 1) {
            unsigned int v;
            do {
                __nanosleep(128);
                asm volatile("ld.acquire.gpu.u32 %0, [%1];"
                             : "=r"(v) : "l"(&g_batch_bar[batch]) : "memory");
            } while (v < CTA_PER_BATCH);
        }
    }
    __syncthreads();

    /* ============ Phase B: 1 query block per warp (indices prefetched) ====== */
    {
        float2 vp = g_vp[base + idx];
        float4 u;
        if (lane == 0) u = g_uncs[blk];

        if (lane >= knb) { vp.x = 0.f; vp.y = 0.f; }
        const float cv = warp_sum(vp.x);
        const float sp = warp_sum(vp.y);

        if (lane == 0) {
            const float nm = sp / fmaxf(cv, 1.0f);
            const bool ok = (u.z > 0.f) && (knb > 0) && (cv > 0.f);
            const float sq = u.y - 2.0f * nm * u.x + nm * nm * u.z;
            sh_sq[wid] = make_float2(ok ? sq : 0.f, ok ? u.z : 0.f);
        }
    }
    __syncthreads();
    if (threadIdx.x == 0) {
        float s = 0.f, q = 0.f;
        #pragma unroll
        for (int i = 0; i < 8; ++i) { s += sh_sq[i].x; q += sh_sq[i].y; }
        g_cta_sq[blockIdx.x] = make_float2(s, q);      /* whole CTA = one batch */
        const unsigned int old = arrive_acq_rel(&g_done);
        is_last = (old == GRID - 1);
    }
    __syncthreads();
    if (!is_last) return;

    /* ============ Phase C: last CTA, 16 KB of partials, fixed order ========= */
    if (wid == 0) {
        float bs = 0.f, bc = 0.f;
        #pragma unroll
        for (int i = 0; i < GRID / 32; ++i) {          /* 32 iterations */
            const float2 p = g_cta_bce[lane + 32 * i];
            bs += p.x; bc += p.y;
        }
        bs = warp_sum(bs);
        bc = warp_sum(bc);
        if (lane == 0) s_bce = bs / fmaxf(bc, 1.0f);
    }

    #pragma unroll
    for (int t = 0; t < 2; ++t) {                      /* warp w -> batches 2w, 2w+1 */
        const int bb = wid * 2 + t;
        float sq = 0.f, qu = 0.f;
        #pragma unroll
        for (int i = 0; i < 2; ++i) {                  /* 64 CTAs per batch */
            const float2 p = g_cta_sq[bb * 64 + i * 32 + lane];
            sq += p.x; qu += p.y;
        }
        sq = warp_sum(sq);
        qu = warp_sum(qu);
        if (lane == 0) { bsq[bb] = sq; bqu[bb] = qu; }
    }
    __syncthreads();

    if (threadIdx.x == 0) {
        float acc = 0.f, nv = 0.f;
        #pragma unroll
        for (int b2 = 0; b2 < BB; ++b2) {
            if (bqu[b2] > 0.0f) {
                acc += bsq[b2] / fmaxf(bqu[b2], 1.0f);
                nv  += 1.0f;
            }
        }
        out[0] = s_bce + GW * (acc / fmaxf(nv, 1.0f));
        /* self-reset for graph replay: every CTA already passed its counters */
        #pragma unroll
        for (int b2 = 0; b2 < BB; ++b2) g_batch_bar[b2] = 0;
        g_done = 0;
    }
}

extern "C" void kernel_launch(void* const* d_in, const int* in_sizes, int n_in,
                              void* d_out, int out_size)
{
    const float4* logits        = (const float4*)d_in[0];
    const float4* targets       = (const float4*)d_in[1];
    const int4*   sup_mask      = (const int4*)d_in[2];
    const int4*   ign_mask      = (const int4*)d_in[3];
    const int*    kv_indices    = (const int*)d_in[4];
    const int*    kv_num_blocks = (const int*)d_in[5];
    float* out = (float*)d_out;

    fused_kernel<<<GRID, TPB>>>(logits, targets, sup_mask, ign_mask,
                                kv_indices, kv_num_blocks, out);
}

// round 10
// speedup vs baseline: 1.0489x; 1.0489x over previous
#include <cuda_runtime.h>
#include <math.h>

#define BB    16
#define NBB   512
#define KK    32
#define NBLK  (BB * NBB)      /* 8192 (b, nb) blocks */
#define GW    0.3f
#define GRID  512             /* 4 CTAs/SM resident (<=64 regs) */
#define TPB   256

/* ---- scratch (device globals; no allocation) ---- */
__device__ float2 g_vp     [NBLK];  /* (cnt_vld, sum_vld_p) */
__device__ float4 g_uncs   [NBLK];  /* (sum_unc_p, sum_unc_p2, cnt_unc, 0) */
__device__ float2 g_cta_bce[GRID];  /* per-CTA (bce_sum, bce_cnt) */
__device__ float2 g_cta_sq [GRID];  /* per-CTA (sq, qu) — one batch per CTA */
__device__ unsigned int g_bar1 = 0;
__device__ unsigned int g_done = 0;

__device__ __forceinline__ float warp_sum(float v) {
    #pragma unroll
    for (int o = 16; o > 0; o >>= 1) v += __shfl_down_sync(0xFFFFFFFFu, v, o);
    return v;
}

/* reduce two floats simultaneously: 2 shfl + 1 packed f32x2 add per level */
__device__ __forceinline__ void warp_sum2(float& a, float& b) {
    unsigned long long p;
    asm("mov.b64 %0, {%1, %2};" : "=l"(p) : "f"(a), "f"(b));
    #pragma unroll
    for (int o = 16; o > 0; o >>= 1) {
        unsigned int lo = (unsigned int)p, hi = (unsigned int)(p >> 32);
        lo = __shfl_down_sync(0xFFFFFFFFu, lo, o);
        hi = __shfl_down_sync(0xFFFFFFFFu, hi, o);
        unsigned long long q = ((unsigned long long)hi << 32) | lo;
        asm("add.rn.f32x2 %0, %1, %2;" : "=l"(p) : "l"(p), "l"(q));
    }
    asm("mov.b64 {%0, %1}, %2;" : "=f"(a), "=f"(b) : "l"(p));
}

__device__ __forceinline__ unsigned int arrive_acq_rel(unsigned int* ctr) {
    unsigned int old;
    asm volatile("atom.acq_rel.gpu.add.u32 %0, [%1], 1;"
                 : "=r"(old) : "l"(ctr) : "memory");
    return old;
}

struct Stats { float svp, sup_, sup2, bce, cnts; };

__device__ __forceinline__ Stats block_stats(const float4& x4, const float4& t4,
                                             const int4& s4, const int4& i4) {
    Stats r = {0.f, 0.f, 0.f, 0.f, 0.f};
    const float xs[4] = {x4.x, x4.y, x4.z, x4.w};
    const float ts[4] = {t4.x, t4.y, t4.z, t4.w};
    const int   ss[4] = {s4.x, s4.y, s4.z, s4.w};
    const int   is_[4]= {i4.x, i4.y, i4.z, i4.w};
    #pragma unroll
    for (int j = 0; j < 4; ++j) {
        const float x  = xs[j];
        const bool  su = ss[j] != 0;
        const bool  ig = is_[j] != 0;
        const bool  vld = !ig;
        const bool  unc = vld && !su;

        const float p = __fdividef(1.0f, 1.0f + __expf(-x));
        if (vld) r.svp += p;
        if (unc) { r.sup_ += p; r.sup2 = fmaf(p, p, r.sup2); }
        /* targets are exactly 0.0 or 1.0: BCE = -log(t ? p : 1-p) */
        if (su)  r.bce -= __logf(ts[j] > 0.5f ? p : 1.0f - p);
        /* pack counts: vld + 256*unc + 65536*sup (sum < 2^24, exact) */
        r.cnts += (vld ? 1.0f : 0.0f) + (unc ? 256.0f : 0.0f) + (su ? 65536.0f : 0.0f);
    }
    return r;
}

__global__ void __launch_bounds__(TPB, 4) fused_kernel(
    const float4* __restrict__ logits,
    const float4* __restrict__ targets,
    const int4*   __restrict__ sup_mask,
    const int4*   __restrict__ ign_mask,
    const int*    __restrict__ kv_indices,
    const int*    __restrict__ kv_num_blocks,
    float*        __restrict__ out)
{
    const int lane  = threadIdx.x & 31;
    const int wid   = threadIdx.x >> 5;
    const int gwarp = blockIdx.x * 8 + wid;      /* owns blocks 2w, 2w+1 */

    __shared__ float2 sh_bce[8];
    __shared__ float2 sh_sq[16];
    __shared__ float  bsq[BB], bqu[BB];
    __shared__ float  s_bce;
    __shared__ bool   is_last;

    const int blk0 = gwarp * 2;
    const int base = (blk0 >> 9) << 9;           /* batch base (both blocks same batch) */

    /* ---- prefetch phase-B operands (latency hides under phase A) ---- */
    const int idx0 = kv_indices[blk0 * KK + lane];
    const int idx1 = kv_indices[(blk0 + 1) * KK + lane];
    const int knb0 = kv_num_blocks[blk0];
    const int knb1 = kv_num_blocks[blk0 + 1];

    /* ============ Phase A: 2 blocks per warp, fully unrolled (MLP=8) ========== */
    {
        const int v0 = blk0 * 32 + lane;
        const int v1 = v0 + 32;

        const float4 xa = logits[v0],   xb = logits[v1];
        const float4 ta = targets[v0],  tb = targets[v1];
        const int4   sa = sup_mask[v0], sb = sup_mask[v1];
        const int4   ia = ign_mask[v0], ib = ign_mask[v1];

        Stats A = block_stats(xa, ta, sa, ia);
        Stats B = block_stats(xb, tb, sb, ib);

        /* 5 packed reduction trees (2 floats each) — halves the FADD count */
        warp_sum2(A.svp,  B.svp);
        warp_sum2(A.sup_, B.sup_);
        warp_sum2(A.sup2, B.sup2);
        warp_sum2(A.bce,  B.bce);
        warp_sum2(A.cnts, B.cnts);

        if (lane == 0) {
            const int ca = (int)A.cnts, cb = (int)B.cnts;
            g_vp  [blk0]     = make_float2((float)(ca & 255), A.svp);
            g_vp  [blk0 + 1] = make_float2((float)(cb & 255), B.svp);
            g_uncs[blk0]     = make_float4(A.sup_, A.sup2, (float)((ca >> 8) & 255), 0.f);
            g_uncs[blk0 + 1] = make_float4(B.sup_, B.sup2, (float)((cb >> 8) & 255), 0.f);
            sh_bce[wid] = make_float2(A.bce + B.bce, (float)((ca >> 16) + (cb >> 16)));
        }
    }
    __syncthreads();
    if (threadIdx.x == 0) {
        float s = 0.f, c = 0.f;
        #pragma unroll
        for (int w = 0; w < 8; ++w) { s += sh_bce[w].x; c += sh_bce[w].y; }
        g_cta_bce[blockIdx.x] = make_float2(s, c);
        const unsigned int old = arrive_acq_rel(&g_bar1);
        if (old != GRID - 1) {
            unsigned int v;
            do {
                asm volatile("ld.acquire.gpu.u32 %0, [%1];"
                             : "=r"(v) : "l"(&g_bar1) : "memory");
            } while (v < GRID);
        }
    }
    __syncthreads();

    /* ============ Phase B: 2 query blocks per warp (indices prefetched) ====== */
    {
        float2 vp0 = g_vp[base + idx0];
        float2 vp1 = g_vp[base + idx1];
        float4 u0, u1;
        if (lane == 0) { u0 = g_uncs[blk0]; u1 = g_uncs[blk0 + 1]; }

        if (lane >= knb0) { vp0.x = 0.f; vp0.y = 0.f; }
        if (lane >= knb1) { vp1.x = 0.f; vp1.y = 0.f; }
        float cv0 = vp0.x, sp0 = vp0.y, cv1 = vp1.x, sp1 = vp1.y;
        warp_sum2(cv0, sp0);
        warp_sum2(cv1, sp1);

        if (lane == 0) {
            const float nm0 = __fdividef(sp0, fmaxf(cv0, 1.0f));
            const float nm1 = __fdividef(sp1, fmaxf(cv1, 1.0f));
            const bool ok0 = (u0.z > 0.f) && (knb0 > 0) && (cv0 > 0.f);
            const bool ok1 = (u1.z > 0.f) && (knb1 > 0) && (cv1 > 0.f);
            const float sq0 = u0.y - 2.0f * nm0 * u0.x + nm0 * nm0 * u0.z;
            const float sq1 = u1.y - 2.0f * nm1 * u1.x + nm1 * nm1 * u1.z;
            sh_sq[wid * 2]     = make_float2(ok0 ? sq0 : 0.f, ok0 ? u0.z : 0.f);
            sh_sq[wid * 2 + 1] = make_float2(ok1 ? sq1 : 0.f, ok1 ? u1.z : 0.f);
        }
    }
    __syncthreads();
    if (threadIdx.x == 0) {
        float s = 0.f, q = 0.f;
        #pragma unroll
        for (int i = 0; i < 16; ++i) { s += sh_sq[i].x; q += sh_sq[i].y; }
        g_cta_sq[blockIdx.x] = make_float2(s, q);     /* whole CTA = one batch */
        const unsigned int old = arrive_acq_rel(&g_done);
        is_last = (old == GRID - 1);
    }
    __syncthreads();
    if (!is_last) return;

    /* ============ Phase C: last CTA, 8 KB of partials, fixed order =========== */
    if (wid == 0) {
        float bs = 0.f, bc = 0.f;
        #pragma unroll
        for (int i = 0; i < GRID / 32; ++i) {         /* 16 iterations */
            const float2 p = g_cta_bce[lane + 32 * i];
            bs += p.x; bc += p.y;
        }
        warp_sum2(bs, bc);
        if (lane == 0) s_bce = __fdividef(bs, fmaxf(bc, 1.0f));
    }

    #pragma unroll
    for (int t = 0; t < 2; ++t) {                     /* warp w -> batches 2w, 2w+1 */
        const int bb = wid * 2 + t;
        const float2 p = g_cta_sq[bb * 32 + lane];    /* 32 CTAs per batch */
        float sq = p.x, qu = p.y;
        warp_sum2(sq, qu);
        if (lane == 0) { bsq[bb] = sq; bqu[bb] = qu; }
    }
    __syncthreads();

    if (threadIdx.x == 0) {
        float acc = 0.f, nv = 0.f;
        #pragma unroll
        for (int b2 = 0; b2 < BB; ++b2) {
            if (bqu[b2] > 0.0f) {
                acc += __fdividef(bsq[b2], fmaxf(bqu[b2], 1.0f));
                nv  += 1.0f;
            }
        }
        out[0] = s_bce + GW * __fdividef(acc, fmaxf(nv, 1.0f));
        g_bar1 = 0;   /* safe: every CTA already passed both counters */
        g_done = 0;
    }
}

extern "C" void kernel_launch(void* const* d_in, const int* in_sizes, int n_in,
                              void* d_out, int out_size)
{
    const float4* logits        = (const float4*)d_in[0];
    const float4* targets       = (const float4*)d_in[1];
    const int4*   sup_mask      = (const int4*)d_in[2];
    const int4*   ign_mask      = (const int4*)d_in[3];
    const int*    kv_indices    = (const int*)d_in[4];
    const int*    kv_num_blocks = (const int*)d_in[5];
    float* out = (float*)d_out;

    fused_kernel<<<GRID, TPB>>>(logits, targets, sup_mask, ign_mask,
                                kv_indices, kv_num_blocks, out);
}